// round 4
// baseline (speedup 1.0000x reference)
#include <cuda_runtime.h>
#include <math.h>

// Problem constants
#define Bn 32
#define CIN 96
#define Tt 288
#define Vv 25
#define Ss 3
#define Cc 96
#define Jn 288           // S*Cout rows of W
#define VP 28            // padded V for z scratch
#define TTc 32           // t's per CTA (pass 1)
#define NT 9             // 288/32
#define JR 292           // row stride sWt/sYt (mult of 4)
#define XR 52            // duplicated-x row stride
#define AR 56            // duplicated-A row stride

typedef unsigned long long ull;

__device__ float  g_z[(size_t)Bn * Cc * Tt * VP];
__device__ double g_psum[Cc * Bn];
__device__ double g_pss [Cc * Bn];
__device__ float  g_mean[Cc];
__device__ float  g_rstd[Cc];

__device__ __forceinline__ void fma2(ull &d, ull a, ull b) {
    asm("fma.rn.f32x2 %0, %1, %2, %0;" : "+l"(d) : "l"(a), "l"(b));
}
__device__ __forceinline__ float lo2(ull v) { return __uint_as_float((unsigned)(v & 0xffffffffull)); }
__device__ __forceinline__ float hi2(ull v) { return __uint_as_float((unsigned)(v >> 32)); }

// ---------------------------------------------------------------------------
// Pass 1: per (b, t-tile). 512 threads. Phases per t (2 syncs):
//   A: BIG (tid 0..503): y[j][m] = sum_k W[j][k]*x[k][m] (+bias) -> sYt
//   B: SMALL (tid 0..335): z[c][m] = sum_{s,n} y[s*96+c][n]*A[s][n][m] -> g_z
//      PF (tid 336..511): stream x(t+1) -> sXd[next], duplicated pairs
// smem (floats):
//   sWt [96][292]  sWt[k][j] = W[j][k]            28032  @0
//   sYt [28][292]  sYt[m][j] = y[j][m]             8176  @28032
//   sXd [2][96][52] dup x pairs                    9984  @36208
//   sAd [75][56]    dup A pairs (m 25..27 = 0)     4200  @46192
//   sB  [288]                                       288  @50392
//   total 50680 floats = 202720 B  (1 CTA/SM, 16 warps)
// ---------------------------------------------------------------------------
__global__ void __launch_bounds__(512, 1)
pass1_kernel(const float* __restrict__ x, const float* __restrict__ A,
             const float* __restrict__ W, const float* __restrict__ bias) {
    extern __shared__ float smem[];
    float* sWt = smem;
    float* sYt = smem + 28032;
    float* sXd = smem + 36208;
    float* sAd = smem + 46192;
    float* sB  = smem + 50392;

    const int tid = threadIdx.x;
    const int t0  = blockIdx.x * TTc;
    const int b   = blockIdx.y;

    // ---- preamble ----
    for (int idx = tid; idx < Jn * CIN; idx += 512) {
        int j = idx / CIN, k = idx % CIN;          // coalesced read of W
        sWt[k * JR + j] = W[idx];
    }
    for (int idx = tid; idx < Ss * Vv * VP; idx += 512) {
        int row = idx / VP, m = idx % VP;
        float a = (m < Vv) ? A[row * Vv + m] : 0.0f;
        sAd[row * AR + 2 * m]     = a;
        sAd[row * AR + 2 * m + 1] = a;
    }
    if (tid < Jn) sB[tid] = bias[tid];
    for (int idx = tid; idx < 2 * CIN * XR; idx += 512) sXd[idx] = 0.0f;
    __syncthreads();
    for (int idx = tid; idx < CIN * Vv; idx += 512) {
        int i = idx / Vv, n = idx % Vv;
        float v = x[((b * CIN + i) * Tt + t0) * Vv + n];
        float2 d; d.x = v; d.y = v;
        *(float2*)(sXd + i * XR + 2 * n) = d;
    }
    __syncthreads();

    // role mappings
    const int mtB = tid % 7;        // BIG: m-tile -> 4 m's
    const int jbB = tid / 7;        // BIG: 0..71  -> 4 j's
    const int mtS = tid % 7;        // SMALL
    const int cbS = tid / 7;        // SMALL: 0..47 -> 2 c's

    for (int tt = 0; tt < TTc; tt++) {
        const int t   = t0 + tt;
        const int cur = tt & 1;
        const int nxt = cur ^ 1;

        // ---- phase A: BIG on 504 threads ----
        if (tid < 504) {
            const int j0 = jbB * 4;
            const int m0 = mtB * 4;
            ull acc[2][4];
#pragma unroll
            for (int p = 0; p < 2; p++)
#pragma unroll
                for (int q = 0; q < 4; q++) acc[p][q] = 0ull;

            const float* wp = sWt + j0;
            const float* xp = sXd + cur * (CIN * XR) + 2 * m0;
#pragma unroll 8
            for (int k = 0; k < CIN; k++) {
                ulonglong2 w  = *(const ulonglong2*)(wp);       // j0..j0+3
                ulonglong2 x0 = *(const ulonglong2*)(xp);       // m0,m0+1 dup
                ulonglong2 x1 = *(const ulonglong2*)(xp + 4);   // m0+2,m0+3 dup
                fma2(acc[0][0], w.x, x0.x); fma2(acc[0][1], w.x, x0.y);
                fma2(acc[0][2], w.x, x1.x); fma2(acc[0][3], w.x, x1.y);
                fma2(acc[1][0], w.y, x0.x); fma2(acc[1][1], w.y, x0.y);
                fma2(acc[1][2], w.y, x1.x); fma2(acc[1][3], w.y, x1.y);
                wp += JR;
                xp += XR;
            }
            const float b0 = sB[j0],     b1 = sB[j0 + 1];
            const float b2 = sB[j0 + 2], b3 = sB[j0 + 3];
#pragma unroll
            for (int q = 0; q < 4; q++) {
                float4 v;
                v.x = lo2(acc[0][q]) + b0;
                v.y = hi2(acc[0][q]) + b1;
                v.z = lo2(acc[1][q]) + b2;
                v.w = hi2(acc[1][q]) + b3;
                *(float4*)(sYt + (m0 + q) * JR + j0) = v;
            }
        }
        __syncthreads();

        // ---- phase B: SMALL (336) + PF (176) ----
        if (tid < 336) {
            const int c0 = cbS * 2;
            const int m0 = mtS * 4;
            ull acc[4] = {0ull, 0ull, 0ull, 0ull};
#pragma unroll
            for (int s = 0; s < Ss; s++) {
                const float* yrow = sYt + s * Cc + c0;
                const float* arow = sAd + s * (Vv * AR) + 2 * m0;
#pragma unroll 5
                for (int n = 0; n < Vv; n++) {
                    ull yy = *(const ull*)(yrow + n * JR);         // c0, c0+1
                    ulonglong2 a0 = *(const ulonglong2*)(arow + n * AR);
                    ulonglong2 a1 = *(const ulonglong2*)(arow + n * AR + 4);
                    fma2(acc[0], yy, a0.x); fma2(acc[1], yy, a0.y);
                    fma2(acc[2], yy, a1.x); fma2(acc[3], yy, a1.y);
                }
            }
            const size_t cstride = (size_t)Tt * VP;
            float* zb = g_z + ((size_t)(b * Cc + c0) * Tt + t) * VP + m0;
            float4 v;
            v.x = lo2(acc[0]); v.y = lo2(acc[1]); v.z = lo2(acc[2]); v.w = lo2(acc[3]);
            *(float4*)(zb) = v;
            v.x = hi2(acc[0]); v.y = hi2(acc[1]); v.z = hi2(acc[2]); v.w = hi2(acc[3]);
            *(float4*)(zb + cstride) = v;
        } else if (tt + 1 < TTc) {
            // PF: 176 threads stream x(t+1), duplicated
            const int tn = t + 1;
            int idx = tid - 336;                  // 0..175
            int i = idx / Vv, n = idx % Vv;
            float* xb = sXd + nxt * (CIN * XR);
            const float* xg = x + ((size_t)b * CIN * Tt + (size_t)tn) * Vv;
#pragma unroll
            for (int r = 0; r < 14; r++) {
                if (idx < CIN * Vv) {
                    float v = xg[i * (Tt * Vv) + n];
                    float2 d; d.x = v; d.y = v;
                    *(float2*)(xb + i * XR + 2 * n) = d;
                }
                idx += 176;
                i += 7; n += 1;                   // +176 = +7*25 + 1
                if (n >= Vv) { n -= Vv; i += 1; }
            }
        }
        __syncthreads();
    }
}

// ---------------------------------------------------------------------------
// Pass 2a: per-(c,b) plane partial BN stats over windowed z.
// ---------------------------------------------------------------------------
__global__ void __launch_bounds__(256)
pass2a_kernel() {
    const int c = blockIdx.x;
    const int b = blockIdx.y;
    const int tid = threadIdx.x;
    __shared__ float sP[Tt * VP];
    __shared__ double red[512];

    const float* src = g_z + (size_t)(b * Cc + c) * Tt * VP;
    for (int i = tid; i < Tt * VP; i += 256) sP[i] = src[i];
    __syncthreads();

    double s = 0.0, q = 0.0;
    int t = tid / Vv, m = tid % Vv;
    for (int it = 0; it < 29; it++) {
        if (t < Tt) {
            float v = 0.0f;
#pragma unroll
            for (int k = -2; k <= 2; k++) {
                int tk = t + k;
                if (tk >= 0 && tk < Tt) v += sP[tk * VP + m];
            }
            v *= 0.2f;
            s += (double)v;
            q += (double)v * (double)v;
        }
        t += 10; m += 6;
        if (m >= Vv) { m -= Vv; t += 1; }
    }
    red[tid] = s; red[256 + tid] = q;
    __syncthreads();
    for (int s2 = 128; s2 > 0; s2 >>= 1) {
        if (tid < s2) {
            red[tid] += red[tid + s2];
            red[256 + tid] += red[256 + tid + s2];
        }
        __syncthreads();
    }
    if (tid == 0) {
        g_psum[c * Bn + b] = red[0];
        g_pss [c * Bn + b] = red[256];
    }
}

// ---------------------------------------------------------------------------
// Pass 2b: reduce 32 partials per channel -> mean/rstd
// ---------------------------------------------------------------------------
__global__ void __launch_bounds__(32)
pass2b_kernel() {
    const int c = blockIdx.x;
    const int lane = threadIdx.x;
    double s = g_psum[c * Bn + lane];
    double q = g_pss [c * Bn + lane];
#pragma unroll
    for (int o = 16; o > 0; o >>= 1) {
        s += __shfl_down_sync(0xffffffffu, s, o);
        q += __shfl_down_sync(0xffffffffu, q, o);
    }
    if (lane == 0) {
        const double N = (double)Bn * Tt * Vv;
        double mean = s / N;
        double var  = q / N - mean * mean;
        g_mean[c] = (float)mean;
        g_rstd[c] = (float)(1.0 / sqrt(var + 1e-5));
    }
}

// ---------------------------------------------------------------------------
// Pass 3: window-avg + normalize + affine + relu
// ---------------------------------------------------------------------------
__global__ void __launch_bounds__(256)
pass3_kernel(const float* __restrict__ gamma, const float* __restrict__ beta,
             float* __restrict__ out) {
    const int c = blockIdx.x;
    const int b = blockIdx.y;
    const int tid = threadIdx.x;
    __shared__ float sP[Tt * VP];

    const float* src = g_z + (size_t)(b * Cc + c) * Tt * VP;
    for (int i = tid; i < Tt * VP; i += 256) sP[i] = src[i];
    __syncthreads();

    const float mean = g_mean[c];
    const float rstd = g_rstd[c];
    const float sc = rstd * gamma[c];
    const float sh = beta[c] - mean * sc;

    float* dst = out + (size_t)(b * Cc + c) * Tt * Vv;
    int t = tid / Vv, m = tid % Vv;
    int i = tid;
    for (int it = 0; it < 29; it++) {
        if (t < Tt) {
            float v = 0.0f;
#pragma unroll
            for (int k = -2; k <= 2; k++) {
                int tk = t + k;
                if (tk >= 0 && tk < Tt) v += sP[tk * VP + m];
            }
            v *= 0.2f;
            float o = fmaf(v, sc, sh);
            dst[i] = fmaxf(o, 0.0f);
        }
        t += 10; m += 6; i += 256;
        if (m >= Vv) { m -= Vv; t += 1; }
    }
}

// ---------------------------------------------------------------------------
extern "C" void kernel_launch(void* const* d_in, const int* in_sizes, int n_in,
                              void* d_out, int out_size) {
    const float* x     = (const float*)d_in[0];
    const float* A     = (const float*)d_in[1];
    const float* W     = (const float*)d_in[2];
    const float* bias  = (const float*)d_in[3];
    const float* gamma = (const float*)d_in[4];
    const float* beta  = (const float*)d_in[5];
    float* out = (float*)d_out;

    const int smem1 = 50680 * 4;   // 202720 bytes
    cudaFuncSetAttribute(pass1_kernel, cudaFuncAttributeMaxDynamicSharedMemorySize, smem1);

    pass1_kernel<<<dim3(NT, Bn), 512, smem1>>>(x, A, W, bias);
    pass2a_kernel<<<dim3(Cc, Bn), 256>>>();
    pass2b_kernel<<<Cc, 32>>>();
    pass3_kernel<<<dim3(Cc, Bn), 256>>>(gamma, beta, out);
}

// round 5
// speedup vs baseline: 2.2456x; 2.2456x over previous
#include <cuda_runtime.h>
#include <math.h>

// Problem constants
#define Bn 32
#define CIN 96
#define Tt 288
#define Vv 25
#define Ss 3
#define Cc 96
#define Oo 288           // S*Cout
#define VP 28            // V padded to 28
#define TTc 32           // t's per CTA in pass 1
#define NT 9             // 288/32
#define WROW 292         // padded row length for sWt / sYt (16B-aligned rows)

typedef unsigned long long ull;

// z scratch, padded layout [b][c][t][28]
__device__ float  g_z[(size_t)Bn * Cc * Tt * VP];
__device__ double g_psum[Cc * Bn];
__device__ double g_pss [Cc * Bn];
__device__ float  g_mean[Cc];
__device__ float  g_rstd[Cc];

__device__ __forceinline__ void fma2(ull &d, ull a, ull b) {
    asm("fma.rn.f32x2 %0, %1, %2, %0;" : "+l"(d) : "l"(a), "l"(b));
}
__device__ __forceinline__ ull dup2(float x) {
    ull r;
    asm("mov.b64 %0, {%1, %1};" : "=l"(r) : "f"(x));
    return r;
}
__device__ __forceinline__ float lo2(ull v) { return __uint_as_float((unsigned)(v & 0xffffffffull)); }
__device__ __forceinline__ float hi2(ull v) { return __uint_as_float((unsigned)(v >> 32)); }

// ---------------------------------------------------------------------------
// Pass 1 (R1 structure + wide-LDS fix): per (b, t-tile):
//   y = W @ x[b,:,t,:] + bias ; z = sum_s y_s @ A_s  -> g_z
// Shared layout (floats):
//   sWt [96][292]   sWt[i][o] = W[o][i]              28032  @0
//   sYt [28][292]   sYt[m][o] = y[o][m]               8176  @28032
//   sX  [2][96][28] double-buffered x slice           5376  @36208
//   sA  [3][25][28] A padded (cols 25..27 = 0)        2100  @41584
//   sB  [288]                                          288  @43684
//   total 43972 floats = 175888 bytes (1 CTA/SM)
// ---------------------------------------------------------------------------
__global__ void __launch_bounds__(256, 1)
pass1_kernel(const float* __restrict__ x, const float* __restrict__ A,
             const float* __restrict__ W, const float* __restrict__ bias) {
    extern __shared__ float smem[];
    float* sWt = smem;                  // 28032
    float* sYt = smem + 28032;          //  8176
    float* sX  = smem + 36208;          //  5376
    float* sA  = smem + 41584;          //  2100
    float* sB  = smem + 43684;          //   288

    const int tid = threadIdx.x;
    const int b   = blockIdx.y;
    const int t0  = blockIdx.x * TTc;

    // ---- load weights (transposed), A (padded), bias ----
    for (int idx = tid; idx < Oo * CIN; idx += 256) {
        int o = idx / CIN, i = idx % CIN;
        sWt[i * WROW + o] = W[idx];
    }
    for (int idx = tid; idx < Ss * Vv * VP; idx += 256) {
        int s = idx / (Vv * VP);
        int r = idx % (Vv * VP);
        int n = r / VP, m = r % VP;
        sA[idx] = (m < Vv) ? A[(s * Vv + n) * Vv + m] : 0.0f;
    }
    for (int idx = tid; idx < Oo; idx += 256) sB[idx] = bias[idx];
    // zero pad columns of both x buffers
    for (int idx = tid; idx < 2 * CIN * (VP - Vv); idx += 256) {
        int buf = idx / (CIN * (VP - Vv));
        int r = idx % (CIN * (VP - Vv));
        int i = r / (VP - Vv), p = r % (VP - Vv);
        sX[buf * (CIN * VP) + i * VP + Vv + p] = 0.0f;
    }
    // initial x slice (t0) into buffer 0
    for (int idx = tid; idx < CIN * Vv; idx += 256) {
        int i = idx / Vv, n = idx % Vv;
        sX[i * VP + n] = x[((b * CIN + i) * Tt + t0) * Vv + n];
    }
    __syncthreads();

    // thread work mapping (identical to R1):
    const int mtB = tid % 7;
    const int obB = tid / 7;
    const int mtS = tid % 7;
    const int cbS = tid / 7;

    for (int tt = 0; tt < TTc; tt++) {
        const int t   = t0 + tt;
        const int buf = tt & 1;
        const int xoff = buf * (CIN * VP);

        // prefetch x slice for t+1 into registers
        float pf[10];
        const bool haveNext = (tt + 1 < TTc);
        if (haveNext) {
            const int tn = t + 1;
#pragma unroll
            for (int r = 0; r < 10; r++) {
                int idx = tid + r * 256;
                if (idx < CIN * Vv) {
                    int i = idx / Vv, n = idx % Vv;
                    pf[r] = x[((b * CIN + i) * Tt + tn) * Vv + n];
                }
            }
        }

        // ---- phase BIG: y[o][m] = sum_k W[o][k]*x[k][m], f32x2 over o-pairs ----
        if (tid < 252) {
            const int o0 = obB * 8;
            const int m0 = mtB * 4;
            ull acc[4][4];
#pragma unroll
            for (int p = 0; p < 4; p++)
#pragma unroll
                for (int j = 0; j < 4; j++) acc[p][j] = 0ull;

            const float* wp = sWt + o0;
            const float* xp = sX + xoff + m0;
#pragma unroll 4
            for (int k = 0; k < CIN; k++) {
                ulonglong2 wA = *(const ulonglong2*)(wp);       // o0..o0+3 (2 pairs)
                ulonglong2 wB = *(const ulonglong2*)(wp + 4);   // o0+4..o0+7
                float4 xv = *(const float4*)(xp);               // m0..m0+3
                ull xd0 = dup2(xv.x);
                ull xd1 = dup2(xv.y);
                ull xd2 = dup2(xv.z);
                ull xd3 = dup2(xv.w);
                fma2(acc[0][0], wA.x, xd0); fma2(acc[0][1], wA.x, xd1);
                fma2(acc[0][2], wA.x, xd2); fma2(acc[0][3], wA.x, xd3);
                fma2(acc[1][0], wA.y, xd0); fma2(acc[1][1], wA.y, xd1);
                fma2(acc[1][2], wA.y, xd2); fma2(acc[1][3], wA.y, xd3);
                fma2(acc[2][0], wB.x, xd0); fma2(acc[2][1], wB.x, xd1);
                fma2(acc[2][2], wB.x, xd2); fma2(acc[2][3], wB.x, xd3);
                fma2(acc[3][0], wB.y, xd0); fma2(acc[3][1], wB.y, xd1);
                fma2(acc[3][2], wB.y, xd2); fma2(acc[3][3], wB.y, xd3);
                wp += WROW;
                xp += VP;
            }
            // epilogue: add bias, store y transposed as two float4's per m
            const float b0 = sB[o0],     b1 = sB[o0 + 1];
            const float b2 = sB[o0 + 2], b3 = sB[o0 + 3];
            const float b4 = sB[o0 + 4], b5 = sB[o0 + 5];
            const float b6 = sB[o0 + 6], b7 = sB[o0 + 7];
#pragma unroll
            for (int j = 0; j < 4; j++) {
                const int m = m0 + j;
                float4 v0, v1;
                v0.x = lo2(acc[0][j]) + b0; v0.y = hi2(acc[0][j]) + b1;
                v0.z = lo2(acc[1][j]) + b2; v0.w = hi2(acc[1][j]) + b3;
                v1.x = lo2(acc[2][j]) + b4; v1.y = hi2(acc[2][j]) + b5;
                v1.z = lo2(acc[3][j]) + b6; v1.w = hi2(acc[3][j]) + b7;
                *(float4*)(sYt + m * WROW + o0)     = v0;
                *(float4*)(sYt + m * WROW + o0 + 4) = v1;
            }
        }
        __syncthreads();   // sYt ready; sX[buf^1] free

        // store prefetched x into the other buffer
        if (haveNext) {
#pragma unroll
            for (int r = 0; r < 10; r++) {
                int idx = tid + r * 256;
                if (idx < CIN * Vv) {
                    int i = idx / Vv, n = idx % Vv;
                    sX[(buf ^ 1) * (CIN * VP) + i * VP + n] = pf[r];
                }
            }
        }

        // ---- phase SMALL: z[c][m] = sum_{s,n} y[s*96+c][n] * A[s][n][m] ----
        if (tid < 168) {
            const int m0 = mtS * 4;
            const int c0 = cbS * 4;
            ull z0[4] = {0ull, 0ull, 0ull, 0ull};
            ull z1[4] = {0ull, 0ull, 0ull, 0ull};
#pragma unroll
            for (int s = 0; s < Ss; s++) {
                const float* yrow = sYt + (s * Cc + c0);
                const float* arow = sA + s * (Vv * VP) + m0;
#pragma unroll 5
                for (int n = 0; n < Vv; n++) {
                    ulonglong2 yy = *(const ulonglong2*)(yrow);   // c0..c0+3
                    float4 av = *(const float4*)(arow);           // m0..m0+3
                    ull a0 = dup2(av.x), a1 = dup2(av.y);
                    ull a2 = dup2(av.z), a3 = dup2(av.w);
                    fma2(z0[0], yy.x, a0); fma2(z0[1], yy.x, a1);
                    fma2(z0[2], yy.x, a2); fma2(z0[3], yy.x, a3);
                    fma2(z1[0], yy.y, a0); fma2(z1[1], yy.y, a1);
                    fma2(z1[2], yy.y, a2); fma2(z1[3], yy.y, a3);
                    yrow += WROW;
                    arow += VP;
                }
            }
            // write z (padded layout), STG.128 per channel
            const size_t cstride = (size_t)Tt * VP;
            float* zb = g_z + ((size_t)(b * Cc + c0) * Tt + t) * VP + m0;
            float4 v;
            v.x = lo2(z0[0]); v.y = lo2(z0[1]); v.z = lo2(z0[2]); v.w = lo2(z0[3]);
            *(float4*)(zb) = v;
            v.x = hi2(z0[0]); v.y = hi2(z0[1]); v.z = hi2(z0[2]); v.w = hi2(z0[3]);
            *(float4*)(zb + cstride) = v;
            v.x = lo2(z1[0]); v.y = lo2(z1[1]); v.z = lo2(z1[2]); v.w = lo2(z1[3]);
            *(float4*)(zb + 2 * cstride) = v;
            v.x = hi2(z1[0]); v.y = hi2(z1[1]); v.z = hi2(z1[2]); v.w = hi2(z1[3]);
            *(float4*)(zb + 3 * cstride) = v;
        }
        __syncthreads();   // sYt consumed; sX[buf^1] written
    }
}

// ---------------------------------------------------------------------------
// Pass 2a: per-(c,b) plane partial BN stats over windowed z.
// ---------------------------------------------------------------------------
__global__ void __launch_bounds__(256)
pass2a_kernel() {
    const int c = blockIdx.x;
    const int b = blockIdx.y;
    const int tid = threadIdx.x;
    __shared__ float sP[Tt * VP];
    __shared__ double red[512];

    const float* src = g_z + (size_t)(b * Cc + c) * Tt * VP;
    for (int i = tid; i < Tt * VP; i += 256) sP[i] = src[i];
    __syncthreads();

    double s = 0.0, q = 0.0;
    int t = tid / Vv, m = tid % Vv;
    for (int it = 0; it < 29; it++) {
        if (t < Tt) {
            float v = 0.0f;
#pragma unroll
            for (int k = -2; k <= 2; k++) {
                int tk = t + k;
                if (tk >= 0 && tk < Tt) v += sP[tk * VP + m];
            }
            v *= 0.2f;
            s += (double)v;
            q += (double)v * (double)v;
        }
        t += 10; m += 6;
        if (m >= Vv) { m -= Vv; t += 1; }
    }
    red[tid] = s; red[256 + tid] = q;
    __syncthreads();
    for (int s2 = 128; s2 > 0; s2 >>= 1) {
        if (tid < s2) {
            red[tid] += red[tid + s2];
            red[256 + tid] += red[256 + tid + s2];
        }
        __syncthreads();
    }
    if (tid == 0) {
        g_psum[c * Bn + b] = red[0];
        g_pss [c * Bn + b] = red[256];
    }
}

// ---------------------------------------------------------------------------
// Pass 2b: reduce 32 partials per channel -> mean/rstd
// ---------------------------------------------------------------------------
__global__ void __launch_bounds__(32)
pass2b_kernel() {
    const int c = blockIdx.x;
    const int lane = threadIdx.x;
    double s = g_psum[c * Bn + lane];
    double q = g_pss [c * Bn + lane];
#pragma unroll
    for (int o = 16; o > 0; o >>= 1) {
        s += __shfl_down_sync(0xffffffffu, s, o);
        q += __shfl_down_sync(0xffffffffu, q, o);
    }
    if (lane == 0) {
        const double N = (double)Bn * Tt * Vv;
        double mean = s / N;
        double var  = q / N - mean * mean;
        g_mean[c] = (float)mean;
        g_rstd[c] = (float)(1.0 / sqrt(var + 1e-5));
    }
}

// ---------------------------------------------------------------------------
// Pass 3: window-avg + normalize + affine + relu
// ---------------------------------------------------------------------------
__global__ void __launch_bounds__(256)
pass3_kernel(const float* __restrict__ gamma, const float* __restrict__ beta,
             float* __restrict__ out) {
    const int c = blockIdx.x;
    const int b = blockIdx.y;
    const int tid = threadIdx.x;
    __shared__ float sP[Tt * VP];

    const float* src = g_z + (size_t)(b * Cc + c) * Tt * VP;
    for (int i = tid; i < Tt * VP; i += 256) sP[i] = src[i];
    __syncthreads();

    const float mean = g_mean[c];
    const float rstd = g_rstd[c];
    const float sc = rstd * gamma[c];
    const float sh = beta[c] - mean * sc;

    float* dst = out + (size_t)(b * Cc + c) * Tt * Vv;
    int t = tid / Vv, m = tid % Vv;
    int i = tid;
    for (int it = 0; it < 29; it++) {
        if (t < Tt) {
            float v = 0.0f;
#pragma unroll
            for (int k = -2; k <= 2; k++) {
                int tk = t + k;
                if (tk >= 0 && tk < Tt) v += sP[tk * VP + m];
            }
            v *= 0.2f;
            float o = fmaf(v, sc, sh);
            dst[i] = fmaxf(o, 0.0f);
        }
        t += 10; m += 6; i += 256;
        if (m >= Vv) { m -= Vv; t += 1; }
    }
}

// ---------------------------------------------------------------------------
extern "C" void kernel_launch(void* const* d_in, const int* in_sizes, int n_in,
                              void* d_out, int out_size) {
    const float* x     = (const float*)d_in[0];
    const float* A     = (const float*)d_in[1];
    const float* W     = (const float*)d_in[2];
    const float* bias  = (const float*)d_in[3];
    const float* gamma = (const float*)d_in[4];
    const float* beta  = (const float*)d_in[5];
    float* out = (float*)d_out;

    const int smem1 = 43972 * 4;   // 175888 bytes
    cudaFuncSetAttribute(pass1_kernel, cudaFuncAttributeMaxDynamicSharedMemorySize, smem1);

    pass1_kernel<<<dim3(NT, Bn), 256, smem1>>>(x, A, W, bias);
    pass2a_kernel<<<dim3(Cc, Bn), 256>>>();
    pass2b_kernel<<<Cc, 32>>>();
    pass3_kernel<<<dim3(Cc, Bn), 256>>>(gamma, beta, out);
}

// round 7
// speedup vs baseline: 3.0275x; 1.3482x over previous
#include <cuda_runtime.h>
#include <cuda_bf16.h>
#include <math.h>
#include <stdint.h>

// Problem constants
#define Bn 32
#define CIN 96
#define Tt 288
#define Vv 25
#define Ss 3
#define Cc 96
#define Oo 288
#define VP 28
#define TTc 32
#define NT 9
#define WROW 292         // sYt row stride (floats)

typedef unsigned long long ull;

__device__ float  g_z[(size_t)Bn * Cc * Tt * VP];
__device__ double g_psum[Cc * Bn];
__device__ double g_pss [Cc * Bn];
__device__ float  g_mean[Cc];
__device__ float  g_rstd[Cc];

// ---------------- smem layout (bytes) ----------------
// sWh [288][104] bf16   59904 @ 0
// sWl [288][104] bf16   59904 @ 59904
// sXk [2buf][2spl][96][40] bf16  4*7680=30720 @ 119808
// sYt [32][292] f32     37376 @ 150528
// sA  [75][28]  f32      8400 @ 187904
// sZB [96][28]  f32     10752 @ 196304
// sAS [84]      f32       336 @ 207056
#define SW_H 0
#define SW_L 59904
#define SXK  119808
#define SXK_ONE 7680
#define SYT  150528
#define SA_  187904
#define SZB  196304
#define SAS  207056
#define SM_TOTAL 207392

__device__ __forceinline__ uint32_t smem_u32(const void* p) {
    uint32_t a;
    asm("{ .reg .u64 t; cvta.to.shared.u64 t, %1; cvt.u32.u64 %0, t; }" : "=r"(a) : "l"(p));
    return a;
}
__device__ __forceinline__ void fma2(ull &d, ull a, ull b) {
    asm("fma.rn.f32x2 %0, %1, %2, %0;" : "+l"(d) : "l"(a), "l"(b));
}
__device__ __forceinline__ ull dup2(float x) {
    ull r; asm("mov.b64 %0, {%1, %1};" : "=l"(r) : "f"(x)); return r;
}
__device__ __forceinline__ ull pack2(float lo, float hi) {
    ull r; asm("mov.b64 %0, {%1, %2};" : "=l"(r) : "f"(lo), "f"(hi)); return r;
}
__device__ __forceinline__ float lo2(ull v) { return __uint_as_float((unsigned)(v & 0xffffffffull)); }
__device__ __forceinline__ float hi2(ull v) { return __uint_as_float((unsigned)(v >> 32)); }

__device__ __forceinline__ void ldsm_x4(uint32_t* r, uint32_t addr) {
    asm volatile("ldmatrix.sync.aligned.m8n8.x4.shared.b16 {%0,%1,%2,%3}, [%4];"
        : "=r"(r[0]), "=r"(r[1]), "=r"(r[2]), "=r"(r[3]) : "r"(addr));
}
__device__ __forceinline__ void ldsm_x4_t(uint32_t* r, uint32_t addr) {
    asm volatile("ldmatrix.sync.aligned.m8n8.x4.trans.shared.b16 {%0,%1,%2,%3}, [%4];"
        : "=r"(r[0]), "=r"(r[1]), "=r"(r[2]), "=r"(r[3]) : "r"(addr));
}
__device__ __forceinline__ void mma_bf16(float* d, const uint32_t* a, const uint32_t* b) {
    asm volatile("mma.sync.aligned.m16n8k16.row.col.f32.bf16.bf16.f32 "
        "{%0,%1,%2,%3}, {%4,%5,%6,%7}, {%8,%9}, {%0,%1,%2,%3};"
        : "+f"(d[0]), "+f"(d[1]), "+f"(d[2]), "+f"(d[3])
        : "r"(a[0]), "r"(a[1]), "r"(a[2]), "r"(a[3]), "r"(b[0]), "r"(b[1]));
}

// ---------------------------------------------------------------------------
// Pass 1: per (b, 32-t tile). 256 threads.
// Phase A (all 8 warps): Y[288 o][32 v] = Wsplit @ Xsplit via mma.sync bf16.
// Phase B: all store x(t+1); tid<168: z = y@A + (bias folded) -> g_z.
// ---------------------------------------------------------------------------
__global__ void __launch_bounds__(256, 1)
pass1_kernel(const float* __restrict__ x, const float* __restrict__ A,
             const float* __restrict__ W, const float* __restrict__ bias) {
    extern __shared__ char sm8[];
    const uint32_t smb = smem_u32(sm8);
    float* sYt = (float*)(sm8 + SYT);
    float* sA  = (float*)(sm8 + SA_);
    float* sZB = (float*)(sm8 + SZB);
    float* sAS = (float*)(sm8 + SAS);

    const int tid = threadIdx.x;
    const int t0  = blockIdx.x * TTc;
    const int b   = blockIdx.y;

    // ---- preamble: W bf16 split ----
    for (int idx = tid; idx < Oo * CIN; idx += 256) {
        int o = idx / CIN, k = idx % CIN;
        float w = W[idx];
        __nv_bfloat16 h = __float2bfloat16(w);
        __nv_bfloat16 l = __float2bfloat16(w - __bfloat162float(h));
        *(__nv_bfloat16*)(sm8 + SW_H + (o * 104 + k) * 2) = h;
        *(__nv_bfloat16*)(sm8 + SW_L + (o * 104 + k) * 2) = l;
    }
    // zero all X buffers (pads v=25..39 stay zero)
    for (int idx = tid; idx < (4 * SXK_ONE) / 4; idx += 256)
        ((uint32_t*)(sm8 + SXK))[idx] = 0u;
    // A padded fp32
    for (int idx = tid; idx < Ss * Vv * VP; idx += 256) {
        int row = idx / VP, m = idx % VP;
        sA[idx] = (m < Vv) ? A[row * Vv + m] : 0.0f;
    }
    __syncthreads();
    // column sums of A per (s, m)
    if (tid < Ss * VP) {
        int s = tid / VP, m = tid % VP;
        float acc = 0.0f;
#pragma unroll
        for (int n = 0; n < Vv; n++) acc += sA[(s * Vv + n) * VP + m];
        sAS[tid] = acc;
    }
    __syncthreads();
    // zb[c][m] = sum_s bias[s*96+c] * sAS[s][m]
    for (int idx = tid; idx < Cc * VP; idx += 256) {
        int c = idx / VP, m = idx % VP;
        sZB[idx] = bias[c] * sAS[m] + bias[Cc + c] * sAS[VP + m]
                 + bias[2 * Cc + c] * sAS[2 * VP + m];
    }

    // per-thread x addressing (10 elements)
    int koff[10], soff[10];
#pragma unroll
    for (int r = 0; r < 10; r++) {
        int idx = tid + r * 256;
        int k = idx / Vv, v = idx - k * Vv;
        koff[r] = (b * CIN + k) * (Tt * Vv) + v;
        soff[r] = k * 40 + v;
    }
    // initial x(t0) -> buf 0
#pragma unroll
    for (int r = 0; r < 10; r++) {
        if (tid + r * 256 < CIN * Vv) {
            float v = x[koff[r] + t0 * Vv];
            __nv_bfloat16 h = __float2bfloat16(v);
            __nv_bfloat16 l = __float2bfloat16(v - __bfloat162float(h));
            *(__nv_bfloat16*)(sm8 + SXK + soff[r] * 2) = h;
            *(__nv_bfloat16*)(sm8 + SXK + SXK_ONE + soff[r] * 2) = l;
        }
    }
    __syncthreads();

    // MMA mapping
    const int w    = tid >> 5;
    const int lane = tid & 31;
    const bool has3 = (w < 2);
    const uint32_t m0t = 2 * w, m1t = 2 * w + 1, m2t = 16 + w;
    const uint32_t alo = ((lane & 15) * 104 + ((lane >> 4) << 3)) * 2;
    const uint32_t blo = (((lane & 7) + (((lane >> 3) & 1) << 3)) * 40 + ((lane >> 4) << 3)) * 2;
    // SMALL mapping
    const int mtS = tid % 7;
    const int cbS = tid / 7;
    // D store mapping
    const int drow = lane >> 2;
    const int dcol = (lane & 3) * 2;

    const uint32_t swh = smb + SW_H;
    const uint32_t swl = smb + SW_L;

    for (int tt = 0; tt < TTc; tt++) {
        const int t   = t0 + tt;
        const int cur = tt & 1;
        const bool hn = (tt + 1 < TTc);

        // issue x(t+1) prefetch
        float pf[10];
        if (hn) {
#pragma unroll
            for (int r = 0; r < 10; r++)
                if (tid + r * 256 < CIN * Vv) pf[r] = x[koff[r] + (t + 1) * Vv];
        }

        // ---- Phase A: BIG via mma.sync ----
        {
            const uint32_t sxh = smb + SXK + (cur * 2) * SXK_ONE;
            const uint32_t sxl = sxh + SXK_ONE;
            float d0[4][4], d1[4][4], d2[4][4];
#pragma unroll
            for (int nt = 0; nt < 4; nt++)
#pragma unroll
                for (int q = 0; q < 4; q++) { d0[nt][q] = 0.f; d1[nt][q] = 0.f; d2[nt][q] = 0.f; }

#pragma unroll
            for (int kc = 0; kc < 6; kc++) {
                const uint32_t kbA = kc * 32;     // k*2 bytes (16 k per chunk)
                const uint32_t kbB = kc * 1280;   // 16 rows * 40 b16 * 2B

                uint32_t ah0[4], ah1[4], ah2[4], al0[4], al1[4], al2[4];
                ldsm_x4(ah0, swh + m0t * 3328 + kbA + alo);
                ldsm_x4(ah1, swh + m1t * 3328 + kbA + alo);
                ldsm_x4(al0, swl + m0t * 3328 + kbA + alo);
                ldsm_x4(al1, swl + m1t * 3328 + kbA + alo);
                if (has3) {
                    ldsm_x4(ah2, swh + m2t * 3328 + kbA + alo);
                    ldsm_x4(al2, swl + m2t * 3328 + kbA + alo);
                }
                uint32_t bh[4][2], bl[4][2], rr[4];
                ldsm_x4_t(rr, sxh + kbB + blo);
                bh[0][0]=rr[0]; bh[0][1]=rr[1]; bh[1][0]=rr[2]; bh[1][1]=rr[3];
                ldsm_x4_t(rr, sxh + kbB + blo + 32);   // v0 = 16
                bh[2][0]=rr[0]; bh[2][1]=rr[1]; bh[3][0]=rr[2]; bh[3][1]=rr[3];
                ldsm_x4_t(rr, sxl + kbB + blo);
                bl[0][0]=rr[0]; bl[0][1]=rr[1]; bl[1][0]=rr[2]; bl[1][1]=rr[3];
                ldsm_x4_t(rr, sxl + kbB + blo + 32);
                bl[2][0]=rr[0]; bl[2][1]=rr[1]; bl[3][0]=rr[2]; bl[3][1]=rr[3];

#pragma unroll
                for (int nt = 0; nt < 4; nt++) {
                    mma_bf16(d0[nt], ah0, bh[nt]);
                    mma_bf16(d0[nt], ah0, bl[nt]);
                    mma_bf16(d0[nt], al0, bh[nt]);
                    mma_bf16(d1[nt], ah1, bh[nt]);
                    mma_bf16(d1[nt], ah1, bl[nt]);
                    mma_bf16(d1[nt], al1, bh[nt]);
                    if (has3) {
                        mma_bf16(d2[nt], ah2, bh[nt]);
                        mma_bf16(d2[nt], ah2, bl[nt]);
                        mma_bf16(d2[nt], al2, bh[nt]);
                    }
                }
            }
            // D -> sYt[v][o]
#pragma unroll
            for (int nt = 0; nt < 4; nt++) {
                float* p0 = sYt + (nt * 8 + dcol) * WROW + m0t * 16 + drow;
                p0[0] = d0[nt][0]; p0[WROW] = d0[nt][1]; p0[8] = d0[nt][2]; p0[WROW + 8] = d0[nt][3];
                float* p1 = sYt + (nt * 8 + dcol) * WROW + m1t * 16 + drow;
                p1[0] = d1[nt][0]; p1[WROW] = d1[nt][1]; p1[8] = d1[nt][2]; p1[WROW + 8] = d1[nt][3];
                if (has3) {
                    float* p2 = sYt + (nt * 8 + dcol) * WROW + m2t * 16 + drow;
                    p2[0] = d2[nt][0]; p2[WROW] = d2[nt][1]; p2[8] = d2[nt][2]; p2[WROW + 8] = d2[nt][3];
                }
            }
        }
        __syncthreads();   // sYt ready; sXk[nxt] free

        // ---- Phase B: store x(t+1), SMALL ----
        if (hn) {
            char* bh8 = sm8 + SXK + ((cur ^ 1) * 2) * SXK_ONE;
#pragma unroll
            for (int r = 0; r < 10; r++) {
                if (tid + r * 256 < CIN * Vv) {
                    __nv_bfloat16 h = __float2bfloat16(pf[r]);
                    __nv_bfloat16 l = __float2bfloat16(pf[r] - __bfloat162float(h));
                    *(__nv_bfloat16*)(bh8 + soff[r] * 2) = h;
                    *(__nv_bfloat16*)(bh8 + SXK_ONE + soff[r] * 2) = l;
                }
            }
        }

        if (tid < 168) {
            const int m0 = mtS * 4;
            const int c0 = cbS * 4;
            ull z0[4], z1[4];
#pragma unroll
            for (int j = 0; j < 4; j++) {
                z0[j] = pack2(sZB[c0 * VP + m0 + j], sZB[(c0 + 1) * VP + m0 + j]);
                z1[j] = pack2(sZB[(c0 + 2) * VP + m0 + j], sZB[(c0 + 3) * VP + m0 + j]);
            }
#pragma unroll
            for (int s = 0; s < Ss; s++) {
                const float* yrow = sYt + s * Cc + c0;
                const float* arow = sA + s * (Vv * VP) + m0;
#pragma unroll 5
                for (int n = 0; n < Vv; n++) {
                    ulonglong2 yy = *(const ulonglong2*)(yrow);
                    float4 av = *(const float4*)(arow);
                    ull a0 = dup2(av.x), a1 = dup2(av.y);
                    ull a2 = dup2(av.z), a3 = dup2(av.w);
                    fma2(z0[0], yy.x, a0); fma2(z0[1], yy.x, a1);
                    fma2(z0[2], yy.x, a2); fma2(z0[3], yy.x, a3);
                    fma2(z1[0], yy.y, a0); fma2(z1[1], yy.y, a1);
                    fma2(z1[2], yy.y, a2); fma2(z1[3], yy.y, a3);
                    yrow += WROW;
                    arow += VP;
                }
            }
            const size_t cstride = (size_t)Tt * VP;
            float* zb = g_z + ((size_t)(b * Cc + c0) * Tt + t) * VP + m0;
            float4 v;
            v.x = lo2(z0[0]); v.y = lo2(z0[1]); v.z = lo2(z0[2]); v.w = lo2(z0[3]);
            *(float4*)(zb) = v;
            v.x = hi2(z0[0]); v.y = hi2(z0[1]); v.z = hi2(z0[2]); v.w = hi2(z0[3]);
            *(float4*)(zb + cstride) = v;
            v.x = lo2(z1[0]); v.y = lo2(z1[1]); v.z = lo2(z1[2]); v.w = lo2(z1[3]);
            *(float4*)(zb + 2 * cstride) = v;
            v.x = hi2(z1[0]); v.y = hi2(z1[1]); v.z = hi2(z1[2]); v.w = hi2(z1[3]);
            *(float4*)(zb + 3 * cstride) = v;
        }
        __syncthreads();   // sYt consumed; sXk[nxt] written
    }
}

// ---------------------------------------------------------------------------
// Pass 2a/2b/3 (proven, unchanged)
// ---------------------------------------------------------------------------
__global__ void __launch_bounds__(256)
pass2a_kernel() {
    const int c = blockIdx.x;
    const int b = blockIdx.y;
    const int tid = threadIdx.x;
    __shared__ float sP[Tt * VP];
    __shared__ double red[512];

    const float* src = g_z + (size_t)(b * Cc + c) * Tt * VP;
    for (int i = tid; i < Tt * VP; i += 256) sP[i] = src[i];
    __syncthreads();

    double s = 0.0, q = 0.0;
    int t = tid / Vv, m = tid % Vv;
    for (int it = 0; it < 29; it++) {
        if (t < Tt) {
            float v = 0.0f;
#pragma unroll
            for (int k = -2; k <= 2; k++) {
                int tk = t + k;
                if (tk >= 0 && tk < Tt) v += sP[tk * VP + m];
            }
            v *= 0.2f;
            s += (double)v;
            q += (double)v * (double)v;
        }
        t += 10; m += 6;
        if (m >= Vv) { m -= Vv; t += 1; }
    }
    red[tid] = s; red[256 + tid] = q;
    __syncthreads();
    for (int s2 = 128; s2 > 0; s2 >>= 1) {
        if (tid < s2) {
            red[tid] += red[tid + s2];
            red[256 + tid] += red[256 + tid + s2];
        }
        __syncthreads();
    }
    if (tid == 0) {
        g_psum[c * Bn + b] = red[0];
        g_pss [c * Bn + b] = red[256];
    }
}

__global__ void __launch_bounds__(32)
pass2b_kernel() {
    const int c = blockIdx.x;
    const int lane = threadIdx.x;
    double s = g_psum[c * Bn + lane];
    double q = g_pss [c * Bn + lane];
#pragma unroll
    for (int o = 16; o > 0; o >>= 1) {
        s += __shfl_down_sync(0xffffffffu, s, o);
        q += __shfl_down_sync(0xffffffffu, q, o);
    }
    if (lane == 0) {
        const double N = (double)Bn * Tt * Vv;
        double mean = s / N;
        double var  = q / N - mean * mean;
        g_mean[c] = (float)mean;
        g_rstd[c] = (float)(1.0 / sqrt(var + 1e-5));
    }
}

__global__ void __launch_bounds__(256)
pass3_kernel(const float* __restrict__ gamma, const float* __restrict__ beta,
             float* __restrict__ out) {
    const int c = blockIdx.x;
    const int b = blockIdx.y;
    const int tid = threadIdx.x;
    __shared__ float sP[Tt * VP];

    const float* src = g_z + (size_t)(b * Cc + c) * Tt * VP;
    for (int i = tid; i < Tt * VP; i += 256) sP[i] = src[i];
    __syncthreads();

    const float mean = g_mean[c];
    const float rstd = g_rstd[c];
    const float sc = rstd * gamma[c];
    const float sh = beta[c] - mean * sc;

    float* dst = out + (size_t)(b * Cc + c) * Tt * Vv;
    int t = tid / Vv, m = tid % Vv;
    int i = tid;
    for (int it = 0; it < 29; it++) {
        if (t < Tt) {
            float v = 0.0f;
#pragma unroll
            for (int k = -2; k <= 2; k++) {
                int tk = t + k;
                if (tk >= 0 && tk < Tt) v += sP[tk * VP + m];
            }
            v *= 0.2f;
            float o = fmaf(v, sc, sh);
            dst[i] = fmaxf(o, 0.0f);
        }
        t += 10; m += 6; i += 256;
        if (m >= Vv) { m -= Vv; t += 1; }
    }
}

// ---------------------------------------------------------------------------
extern "C" void kernel_launch(void* const* d_in, const int* in_sizes, int n_in,
                              void* d_out, int out_size) {
    const float* x     = (const float*)d_in[0];
    const float* A     = (const float*)d_in[1];
    const float* W     = (const float*)d_in[2];
    const float* bias  = (const float*)d_in[3];
    const float* gamma = (const float*)d_in[4];
    const float* beta  = (const float*)d_in[5];
    float* out = (float*)d_out;

    cudaFuncSetAttribute(pass1_kernel, cudaFuncAttributeMaxDynamicSharedMemorySize, SM_TOTAL);

    pass1_kernel<<<dim3(NT, Bn), 256, SM_TOTAL>>>(x, A, W, bias);
    pass2a_kernel<<<dim3(Cc, Bn), 256>>>();
    pass2b_kernel<<<Cc, 32>>>();
    pass3_kernel<<<dim3(Cc, Bn), 256>>>(gamma, beta, out);
}